// round 15
// baseline (speedup 1.0000x reference)
#include <cuda_runtime.h>
#include <cuda_fp16.h>
#include <cstdint>

#define B_   4
#define S_   1024
#define D_   2048
#define H_   32
#define KVH_ 8
#define HD_  64

// GEMM: K-step 32, 3 smem stages (R12 proven shape)
#define NSTG   3
#define ASTG32 5120   // halves per stage per matrix: 128 * 40

// ---------------- device scratch ----------------
__device__ __half g_qh[B_ * S_ * H_ * HD_];   // raw Q (rope applied in flash)
__device__ __half g_kh[B_ * S_ * KVH_ * HD_]; // roped K (rope fused in qkv epilogue)
__device__ __half g_vh[B_ * S_ * KVH_ * HD_];
__device__ __half g_attnh[B_ * S_ * H_ * HD_];
__device__ __half g_xh[B_ * S_ * D_];
__device__ __half g_Wqh[2048 * 2048];   // transposed [N][K]
__device__ __half g_Wkh[512 * 2048];
__device__ __half g_Wvh[512 * 2048];
__device__ __half g_Woh[2048 * 2048];

__device__ __forceinline__ uint32_t smem_u32(const void* p) {
    uint32_t a;
    asm("{ .reg .u64 t; cvta.to.shared.u64 t, %1; cvt.u32.u64 %0, t; }"
        : "=r"(a) : "l"(p));
    return a;
}
__device__ __forceinline__ void cpa16(uint32_t dst, const void* src) {
    asm volatile("cp.async.cg.shared.global [%0], [%1], 16;" :: "r"(dst), "l"(src));
}
#define CP_COMMIT() asm volatile("cp.async.commit_group;" ::: "memory")
#define CP_WAIT(n)  asm volatile("cp.async.wait_group %0;" :: "n"(n) : "memory")

__device__ __forceinline__ uint32_t packh2(float a, float b) {
    __half2 h = __floats2half2_rn(a, b);
    return *(uint32_t*)&h;
}
__device__ __forceinline__ uint32_t ex2_h2(float a, float b) {
    __half2 e = __floats2half2_rn(a, b);
    uint32_t u = *(uint32_t*)&e, r;
    asm("ex2.approx.f16x2 %0, %1;" : "=r"(r) : "r"(u));
    return r;
}
__device__ __forceinline__ void mma_f16(float* d, const uint32_t* a, const uint32_t* b) {
    asm volatile(
        "mma.sync.aligned.m16n8k16.row.col.f32.f16.f16.f32 "
        "{%0,%1,%2,%3}, {%4,%5,%6,%7}, {%8,%9}, {%0,%1,%2,%3};"
        : "+f"(d[0]), "+f"(d[1]), "+f"(d[2]), "+f"(d[3])
        : "r"(a[0]), "r"(a[1]), "r"(a[2]), "r"(a[3]), "r"(b[0]), "r"(b[1]));
}
__device__ __forceinline__ void ldsm4(uint32_t* r, uint32_t addr) {
    asm volatile("ldmatrix.sync.aligned.m8n8.x4.shared.b16 {%0,%1,%2,%3}, [%4];"
        : "=r"(r[0]), "=r"(r[1]), "=r"(r[2]), "=r"(r[3]) : "r"(addr));
}
__device__ __forceinline__ void ldsm4t(uint32_t* r, uint32_t addr) {
    asm volatile("ldmatrix.sync.aligned.m8n8.x4.trans.shared.b16 {%0,%1,%2,%3}, [%4];"
        : "=r"(r[0]), "=r"(r[1]), "=r"(r[2]), "=r"(r[3]) : "r"(addr));
}

// ---------------------------------------------------------------------------
// Merged prep: z<4 -> weight transpose+f16 (half2-coalesced stores);
//              z==4 -> x f32->f16 copy (4x float4 per thread)
// ---------------------------------------------------------------------------
__global__ void prep_kernel(const float* __restrict__ x,
                            const float* __restrict__ Wq, const float* __restrict__ Wk,
                            const float* __restrict__ Wv, const float* __restrict__ Wo,
                            __half* __restrict__ xh,
                            __half* __restrict__ dq, __half* __restrict__ dk,
                            __half* __restrict__ dv, __half* __restrict__ dob)
{
    const int z = blockIdx.z;
    const int tx = threadIdx.x, ty = threadIdx.y;   // 32 x 8

    if (z == 4) {
        // x: 8,388,608 floats = 2,097,152 float4; 4096 blocks x 256 thr x 2,
        // issued as 2 independent loads up-front (MLP)
        int bid = blockIdx.y * 64 + blockIdx.x;
        int i = bid * 256 + ty * 32 + tx;
        float4 v0 = *(const float4*)(x + (size_t)i * 4);
        float4 v1 = *(const float4*)(x + (size_t)(i + 1048576) * 4);
        uint2 o0, o1;
        o0.x = packh2(v0.x, v0.y); o0.y = packh2(v0.z, v0.w);
        o1.x = packh2(v1.x, v1.y); o1.y = packh2(v1.z, v1.w);
        *(uint2*)(xh + (size_t)i * 4) = o0;
        *(uint2*)(xh + (size_t)(i + 1048576) * 4) = o1;
        return;
    }

    const float* src; __half* dst; int cols;
    if (z == 0)      { src = Wq; dst = dq;  cols = 2048; }
    else if (z == 1) { src = Wk; dst = dk;  cols = 512;  }
    else if (z == 2) { src = Wv; dst = dv;  cols = 512;  }
    else             { src = Wo; dst = dob; cols = 2048; }
    int bx = blockIdx.x * 32, by = blockIdx.y * 32;
    if (bx >= cols) return;

    __shared__ float t[32][33];
    #pragma unroll
    for (int j = 0; j < 32; j += 8)
        t[ty + j][tx] = src[(size_t)(by + ty + j) * cols + bx + tx];
    __syncthreads();

    // coalesced stores: thread -> half2 (two source rows by+2cp, by+2cp+1)
    // out row o = ty + rowsel*8 + j (rowsel = tx>>4), col pair cp = tx&15
    const int cp = tx & 15, rowsel = tx >> 4;
    #pragma unroll
    for (int j = 0; j < 32; j += 16) {
        int o = ty + rowsel * 8 + j;
        __half2 v = __floats2half2_rn(t[2 * cp][o], t[2 * cp + 1][o]);
        *(__half2*)&dst[(size_t)(bx + o) * 2048 + by + 2 * cp] = v;
    }
}

// ---------------------------------------------------------------------------
// fp16 mma.sync GEMM: K-step 32, 3-stage cp.async, ldmatrix (R12 shape).
// ROPE_K: epilogue stages tile in smem, applies RoPE across (d, d+32) pairs.
// ---------------------------------------------------------------------------
template<bool HALF_OUT, bool ROPE_K>
__device__ __forceinline__ void gemm128_h(
    const __half* __restrict__ A, const __half* __restrict__ Wt,
    void* __restrict__ C, int ldc, int row0, int wc0,
    const float* __restrict__ cosb, const float* __restrict__ sinb)
{
    extern __shared__ __align__(16) __half smh[];
    const uint32_t asb = smem_u32(smh);
    const uint32_t bsb = asb + NSTG * ASTG32 * 2;

    const int tid = threadIdx.x;
    const int wid = tid >> 5, lane = tid & 31;
    const int g = lane >> 2, c = lane & 3;
    const int wm = (wid & 1) * 64;
    const int wn = (wid >> 1) * 32;
    const int l7 = lane & 7, lb = (lane >> 3) & 1, lh = lane >> 4;

    const int lrow = tid >> 1, seg = tid & 1;
    const __half* asrc = A  + (size_t)(row0 + lrow) * 2048 + seg * 16;
    const __half* bsrc = Wt + (size_t)(wc0 + lrow) * 2048 + seg * 16;
    const uint32_t adst = asb + (lrow * 40 + seg * 16) * 2;
    const uint32_t bdst = bsb + (lrow * 40 + seg * 16) * 2;

    float acc[4][4][4];
    #pragma unroll
    for (int mt = 0; mt < 4; mt++)
        #pragma unroll
        for (int nt = 0; nt < 4; nt++)
            #pragma unroll
            for (int e = 0; e < 4; e++) acc[mt][nt][e] = 0.f;

    #pragma unroll
    for (int s = 0; s < NSTG - 1; s++) {
        cpa16(adst + s * ASTG32 * 2,      asrc + s * 32);
        cpa16(adst + s * ASTG32 * 2 + 16, asrc + s * 32 + 8);
        cpa16(bdst + s * ASTG32 * 2,      bsrc + s * 32);
        cpa16(bdst + s * ASTG32 * 2 + 16, bsrc + s * 32 + 8);
        CP_COMMIT();
    }

    int buf = 0;
    for (int i = 0; i < 64; ++i) {
        CP_WAIT(1);
        __syncthreads();

        const uint32_t Ab = asb + buf * ASTG32 * 2;
        const uint32_t Bb = bsb + buf * ASTG32 * 2;
        #pragma unroll
        for (int kc = 0; kc < 2; kc++) {
            uint32_t af[4][4], bf[2][4];
            #pragma unroll
            for (int mt = 0; mt < 4; mt++)
                ldsm4(af[mt], Ab + ((wm + mt * 16 + l7 + lb * 8) * 40 + kc * 16 + lh * 8) * 2);
            #pragma unroll
            for (int ntp = 0; ntp < 2; ntp++)
                ldsm4(bf[ntp], Bb + ((wn + ntp * 16 + lh * 8 + l7) * 40 + kc * 16 + lb * 8) * 2);
            #pragma unroll
            for (int mt = 0; mt < 4; mt++) {
                #pragma unroll
                for (int ntp = 0; ntp < 2; ntp++) {
                    mma_f16(acc[mt][ntp * 2],     af[mt], &bf[ntp][0]);
                    mma_f16(acc[mt][ntp * 2 + 1], af[mt], &bf[ntp][2]);
                }
            }
        }

        int nk = i + NSTG - 1;
        if (nk < 64) {
            int s = buf + 2 >= NSTG ? buf + 2 - NSTG : buf + 2;
            cpa16(adst + s * ASTG32 * 2,      asrc + nk * 32);
            cpa16(adst + s * ASTG32 * 2 + 16, asrc + nk * 32 + 8);
            cpa16(bdst + s * ASTG32 * 2,      bsrc + nk * 32);
            cpa16(bdst + s * ASTG32 * 2 + 16, bsrc + nk * 32 + 8);
        }
        CP_COMMIT();
        buf = buf + 1 >= NSTG ? 0 : buf + 1;
    }

    if (ROPE_K) {
        __half* st = smh;   // [128][132] = 33792 B, fits in 61440 B
        __syncthreads();    // pipeline reads done; smem free
        #pragma unroll
        for (int mt = 0; mt < 4; mt++) {
            int r = wm + mt * 16 + g;
            #pragma unroll
            for (int nt = 0; nt < 4; nt++) {
                int cl = wn + nt * 8 + 2 * c;
                *(uint32_t*)&st[r * 132 + cl] =
                    packh2(acc[mt][nt][0], acc[mt][nt][1]);
                *(uint32_t*)&st[(r + 8) * 132 + cl] =
                    packh2(acc[mt][nt][2], acc[mt][nt][3]);
            }
        }
        __syncthreads();
        __half* Ch = (__half*)C;
        for (int idx = tid; idx < 8192; idx += 256) {
            int row = idx >> 6, t6 = idx & 63;
            int hd = t6 >> 5, d = t6 & 31;
            int cl = hd * 64 + d;
            float x1 = __half2float(st[row * 132 + cl]);
            float x2 = __half2float(st[row * 132 + cl + 32]);
            int s = (row0 + row) & (S_ - 1);
            float c1 = cosb[s * 64 + d],      s1 = sinb[s * 64 + d];
            float c2 = cosb[s * 64 + d + 32], s2 = sinb[s * 64 + d + 32];
            Ch[(size_t)(row0 + row) * ldc + wc0 + cl]      = __float2half(x1 * c1 - x2 * s1);
            Ch[(size_t)(row0 + row) * ldc + wc0 + cl + 32] = __float2half(x2 * c2 + x1 * s2);
        }
        return;
    }

    #pragma unroll
    for (int mt = 0; mt < 4; mt++) {
        int r = row0 + wm + mt * 16 + g;
        #pragma unroll
        for (int nt = 0; nt < 4; nt++) {
            int col = wc0 + wn + nt * 8 + 2 * c;
            if (HALF_OUT) {
                __half* Ch = (__half*)C;
                *(uint32_t*)&Ch[(size_t)r * ldc + col] =
                    packh2(acc[mt][nt][0], acc[mt][nt][1]);
                *(uint32_t*)&Ch[(size_t)(r + 8) * ldc + col] =
                    packh2(acc[mt][nt][2], acc[mt][nt][3]);
            } else {
                float* Cf = (float*)C;
                *(float2*)&Cf[(size_t)r * ldc + col] =
                    make_float2(acc[mt][nt][0], acc[mt][nt][1]);
                *(float2*)&Cf[(size_t)(r + 8) * ldc + col] =
                    make_float2(acc[mt][nt][2], acc[mt][nt][3]);
            }
        }
    }
}

__global__ __launch_bounds__(256, 2) void qkv_gemm_h(
    const float* __restrict__ cosb, const float* __restrict__ sinb)
{
    int col0 = blockIdx.x * 128, row0 = blockIdx.y * 128;
    if (col0 < 2048) {
        gemm128_h<true, false>(g_xh, g_Wqh, g_qh, 2048, row0, col0, cosb, sinb);
    } else if (col0 < 2560) {
        gemm128_h<true, true>(g_xh, g_Wkh, g_kh, 512, row0, col0 - 2048, cosb, sinb);
    } else {
        gemm128_h<true, false>(g_xh, g_Wvh, g_vh, 512, row0, col0 - 2560, cosb, sinb);
    }
}

__global__ __launch_bounds__(256, 2) void out_gemm_h(float* __restrict__ out)
{
    int col0 = blockIdx.x * 128, row0 = blockIdx.y * 128;
    gemm128_h<false, false>(g_attnh, g_Woh, out, 2048, row0, col0, nullptr, nullptr);
}

// ---------------------------------------------------------------------------
// Flash attention fp16: 3-stage cp.async, one barrier/tile, ldmatrix,
// RoPE-Q fused, exp2-domain softmax via packed ex2.approx.f16x2. (R12)
// ---------------------------------------------------------------------------
#define FSTG 9216   // bytes per stage per matrix: 64*72*2
#define QSCALE 0.180336880f   // 0.125 * log2(e)

__global__ __launch_bounds__(256, 2) void flash_h_kernel(
    const float* __restrict__ cosb, const float* __restrict__ sinb)
{
    extern __shared__ __align__(16) __half fsm[];
    const uint32_t skb = smem_u32(fsm);
    const uint32_t svb = skb + 3 * FSTG;

    const int tid = threadIdx.x;
    const int wid = tid >> 5, lane = tid & 31;
    const int g = lane >> 2, c = lane & 3;
    const int l7 = lane & 7, lb = (lane >> 3) & 1, lh = lane >> 4;
    const int qb = blockIdx.x, h = blockIdx.y, b = blockIdx.z;
    const int kvh = h >> 2;

    const __half* kvK = g_kh + ((size_t)(b * S_) * KVH_ + kvh) * 64;
    const __half* kvV = g_vh + ((size_t)(b * S_) * KVH_ + kvh) * 64;
    const int r0c = tid >> 3, c8 = tid & 7;

    const __half* qr = g_qh + ((size_t)(b * S_ + qb * 128 + wid * 16) * H_ + h) * 64;
    const int s0 = qb * 128 + wid * 16 + g;
    uint32_t qa[4][4];
    #pragma unroll
    for (int kc = 0; kc < 4; kc++) {
        #pragma unroll
        for (int e = 0; e < 4; e++) {
            const int rr = (e & 1) ? (g + 8) : g;
            const int sidx = (e & 1) ? (s0 + 8) : s0;
            const int d = kc * 16 + 2 * c + ((e >> 1) ? 8 : 0);
            __half2 qv = *(const __half2*)&qr[(size_t)rr * 2048 + d];
            __half2 pv = *(const __half2*)&qr[(size_t)rr * 2048 + (d ^ 32)];
            float2 cs = *(const float2*)&cosb[sidx * 64 + d];
            float2 sn = *(const float2*)&sinb[sidx * 64 + d];
            float sgn = (d < 32) ? -1.f : 1.f;
            float r0v = (__half2float(qv.x) * cs.x + sgn * __half2float(pv.x) * sn.x) * QSCALE;
            float r1v = (__half2float(qv.y) * cs.y + sgn * __half2float(pv.y) * sn.y) * QSCALE;
            qa[kc][e] = packh2(r0v, r1v);
        }
    }

    float o[8][4];
    #pragma unroll
    for (int dt = 0; dt < 8; dt++)
        #pragma unroll
        for (int e = 0; e < 4; e++) o[dt][e] = 0.f;
    float m0 = -1.0e30f, m1 = -1.0e30f, l0 = 0.f, l1 = 0.f;

    #pragma unroll
    for (int s = 0; s < 2; s++) {
        const __half* kb = kvK + (size_t)s * 64 * 512;
        const __half* vb = kvV + (size_t)s * 64 * 512;
        #pragma unroll
        for (int u = 0; u < 2; u++) {
            int r = r0c + u * 32;
            cpa16(skb + s * FSTG + (r * 72 + c8 * 8) * 2, kb + (size_t)r * 512 + c8 * 8);
            cpa16(svb + s * FSTG + (r * 72 + c8 * 8) * 2, vb + (size_t)r * 512 + c8 * 8);
        }
        CP_COMMIT();
    }

    int stage = 0;
    for (int jt = 0; jt < 16; ++jt) {
        CP_WAIT(1);
        __syncthreads();

        const uint32_t Kb = skb + stage * FSTG;
        const uint32_t Vb = svb + stage * FSTG;

        float s[8][4];
        #pragma unroll
        for (int nt = 0; nt < 8; nt++)
            #pragma unroll
            for (int e = 0; e < 4; e++) s[nt][e] = 0.f;
        #pragma unroll
        for (int nt = 0; nt < 8; nt++) {
            #pragma unroll
            for (int kc2 = 0; kc2 < 2; kc2++) {
                uint32_t bk[4];
                ldsm4(bk, Kb + ((nt * 8 + l7) * 72 + kc2 * 32 + (lane >> 3) * 8) * 2);
                mma_f16(s[nt], qa[kc2 * 2],     &bk[0]);
                mma_f16(s[nt], qa[kc2 * 2 + 1], &bk[2]);
            }
        }

        float tm0 = -1.0e30f, tm1 = -1.0e30f;
        #pragma unroll
        for (int nt = 0; nt < 8; nt++) {
            tm0 = fmaxf(tm0, fmaxf(s[nt][0], s[nt][1]));
            tm1 = fmaxf(tm1, fmaxf(s[nt][2], s[nt][3]));
        }
        tm0 = fmaxf(tm0, __shfl_xor_sync(0xffffffffu, tm0, 1));
        tm0 = fmaxf(tm0, __shfl_xor_sync(0xffffffffu, tm0, 2));
        tm1 = fmaxf(tm1, __shfl_xor_sync(0xffffffffu, tm1, 1));
        tm1 = fmaxf(tm1, __shfl_xor_sync(0xffffffffu, tm1, 2));

        float nm0 = fmaxf(m0, tm0), nm1 = fmaxf(m1, tm1);
        float al0 = exp2f(m0 - nm0), al1 = exp2f(m1 - nm1);
        m0 = nm0; m1 = nm1;

        uint32_t pk0[8], pk1[8];
        float sum0 = 0.f, sum1 = 0.f;
        #pragma unroll
        for (int nt = 0; nt < 8; nt++) {
            pk0[nt] = ex2_h2(s[nt][0] - nm0, s[nt][1] - nm0);
            pk1[nt] = ex2_h2(s[nt][2] - nm1, s[nt][3] - nm1);
            float2 f0 = __half22float2(*(__half2*)&pk0[nt]);
            float2 f1 = __half22float2(*(__half2*)&pk1[nt]);
            sum0 += f0.x + f0.y;
            sum1 += f1.x + f1.y;
        }
        sum0 += __shfl_xor_sync(0xffffffffu, sum0, 1);
        sum0 += __shfl_xor_sync(0xffffffffu, sum0, 2);
        sum1 += __shfl_xor_sync(0xffffffffu, sum1, 1);
        sum1 += __shfl_xor_sync(0xffffffffu, sum1, 2);
        l0 = l0 * al0 + sum0;
        l1 = l1 * al1 + sum1;

        #pragma unroll
        for (int dt = 0; dt < 8; dt++) {
            o[dt][0] *= al0; o[dt][1] *= al0;
            o[dt][2] *= al1; o[dt][3] *= al1;
        }

        #pragma unroll
        for (int kc = 0; kc < 4; kc++) {
            uint32_t a[4] = { pk0[2 * kc], pk1[2 * kc], pk0[2 * kc + 1], pk1[2 * kc + 1] };
            #pragma unroll
            for (int dtp = 0; dtp < 4; dtp++) {
                uint32_t bv[4];
                ldsm4t(bv, Vb + ((kc * 16 + lb * 8 + l7) * 72 + dtp * 16 + lh * 8) * 2);
                mma_f16(o[dtp * 2],     a, &bv[0]);
                mma_f16(o[dtp * 2 + 1], a, &bv[2]);
            }
        }

        if (jt + 2 < 16) {
            const int ws = (stage + 2 >= 3) ? (stage + 2 - 3) : (stage + 2);
            const __half* kb = kvK + (size_t)(jt + 2) * 64 * 512;
            const __half* vb = kvV + (size_t)(jt + 2) * 64 * 512;
            #pragma unroll
            for (int u = 0; u < 2; u++) {
                int r = r0c + u * 32;
                cpa16(skb + ws * FSTG + (r * 72 + c8 * 8) * 2, kb + (size_t)r * 512 + c8 * 8);
                cpa16(svb + ws * FSTG + (r * 72 + c8 * 8) * 2, vb + (size_t)r * 512 + c8 * 8);
            }
        }
        CP_COMMIT();
        stage = (stage + 1 >= 3) ? 0 : stage + 1;
    }

    float inv0 = 1.f / l0, inv1 = 1.f / l1;
    __half* obase = g_attnh + ((size_t)(b * S_ + qb * 128 + wid * 16) * H_ + h) * 64;
    #pragma unroll
    for (int dt = 0; dt < 8; dt++) {
        *(uint32_t*)&obase[(size_t)g * 2048 + dt * 8 + 2 * c] =
            packh2(o[dt][0] * inv0, o[dt][1] * inv0);
        *(uint32_t*)&obase[(size_t)(g + 8) * 2048 + dt * 8 + 2 * c] =
            packh2(o[dt][2] * inv1, o[dt][3] * inv1);
    }
}

// ---------------------------------------------------------------------------
extern "C" void kernel_launch(void* const* d_in, const int* in_sizes, int n_in,
                              void* d_out, int out_size)
{
    (void)in_sizes; (void)n_in; (void)out_size;
    const float* x   = (const float*)d_in[0];
    const float* cb  = (const float*)d_in[1];
    const float* sb  = (const float*)d_in[2];
    const float* Wq  = (const float*)d_in[3];
    const float* Wk  = (const float*)d_in[4];
    const float* Wv  = (const float*)d_in[5];
    const float* Wo  = (const float*)d_in[6];
    float* out = (float*)d_out;

    const int GEMM_SMEM  = NSTG * ASTG32 * 2 * 2;    // 61440 B -> 2 CTAs/SM
    const int FLASH_SMEM = 6 * FSTG;                  // 55296 B
    cudaFuncSetAttribute(qkv_gemm_h, cudaFuncAttributeMaxDynamicSharedMemorySize, GEMM_SMEM);
    cudaFuncSetAttribute(out_gemm_h, cudaFuncAttributeMaxDynamicSharedMemorySize, GEMM_SMEM);
    cudaFuncSetAttribute(flash_h_kernel, cudaFuncAttributeMaxDynamicSharedMemorySize, FLASH_SMEM);

    __half* xh; __half* wqh; __half* wkh; __half* wvh; __half* woh;
    cudaGetSymbolAddress((void**)&xh,  g_xh);
    cudaGetSymbolAddress((void**)&wqh, g_Wqh);
    cudaGetSymbolAddress((void**)&wkh, g_Wkh);
    cudaGetSymbolAddress((void**)&wvh, g_Wvh);
    cudaGetSymbolAddress((void**)&woh, g_Woh);

    dim3 tb(32, 8);
    prep_kernel<<<dim3(64, 64, 5), tb>>>(x, Wq, Wk, Wv, Wo, xh, wqh, wkh, wvh, woh);

    qkv_gemm_h<<<dim3(3072 / 128, 4096 / 128), 256, GEMM_SMEM>>>(cb, sb);

    flash_h_kernel<<<dim3(S_ / 128, H_, B_), 256, FLASH_SMEM>>>(cb, sb);

    out_gemm_h<<<dim3(2048 / 128, 4096 / 128), 256, GEMM_SMEM>>>(out);
}

// round 16
// speedup vs baseline: 1.0054x; 1.0054x over previous
#include <cuda_runtime.h>
#include <cuda_fp16.h>
#include <cstdint>

#define B_   4
#define S_   1024
#define D_   2048
#define H_   32
#define KVH_ 8
#define HD_  64

// GEMM: K-step 32, 3 smem stages (R12 proven shape)
#define NSTG   3
#define ASTG32 5120   // halves per stage per matrix: 128 * 40

// ---------------- device scratch ----------------
__device__ __half g_qh[B_ * S_ * H_ * HD_];   // raw Q (rope applied in flash)
__device__ __half g_kh[B_ * S_ * KVH_ * HD_]; // roped K (rope fused in qkv epilogue)
__device__ __half g_vh[B_ * S_ * KVH_ * HD_];
__device__ __half g_attnh[B_ * S_ * H_ * HD_];
__device__ __half g_xh[B_ * S_ * D_];
__device__ __half g_Wqh[2048 * 2048];   // transposed [N][K]
__device__ __half g_Wkh[512 * 2048];
__device__ __half g_Wvh[512 * 2048];
__device__ __half g_Woh[2048 * 2048];

__device__ __forceinline__ uint32_t smem_u32(const void* p) {
    uint32_t a;
    asm("{ .reg .u64 t; cvta.to.shared.u64 t, %1; cvt.u32.u64 %0, t; }"
        : "=r"(a) : "l"(p));
    return a;
}
__device__ __forceinline__ void cpa16(uint32_t dst, const void* src) {
    asm volatile("cp.async.cg.shared.global [%0], [%1], 16;" :: "r"(dst), "l"(src));
}
#define CP_COMMIT() asm volatile("cp.async.commit_group;" ::: "memory")
#define CP_WAIT(n)  asm volatile("cp.async.wait_group %0;" :: "n"(n) : "memory")

__device__ __forceinline__ uint32_t packh2(float a, float b) {
    __half2 h = __floats2half2_rn(a, b);
    return *(uint32_t*)&h;
}
__device__ __forceinline__ uint32_t ex2_h2(float a, float b) {
    __half2 e = __floats2half2_rn(a, b);
    uint32_t u = *(uint32_t*)&e, r;
    asm("ex2.approx.f16x2 %0, %1;" : "=r"(r) : "r"(u));
    return r;
}
__device__ __forceinline__ void mma_f16(float* d, const uint32_t* a, const uint32_t* b) {
    asm volatile(
        "mma.sync.aligned.m16n8k16.row.col.f32.f16.f16.f32 "
        "{%0,%1,%2,%3}, {%4,%5,%6,%7}, {%8,%9}, {%0,%1,%2,%3};"
        : "+f"(d[0]), "+f"(d[1]), "+f"(d[2]), "+f"(d[3])
        : "r"(a[0]), "r"(a[1]), "r"(a[2]), "r"(a[3]), "r"(b[0]), "r"(b[1]));
}
__device__ __forceinline__ void ldsm4(uint32_t* r, uint32_t addr) {
    asm volatile("ldmatrix.sync.aligned.m8n8.x4.shared.b16 {%0,%1,%2,%3}, [%4];"
        : "=r"(r[0]), "=r"(r[1]), "=r"(r[2]), "=r"(r[3]) : "r"(addr));
}
__device__ __forceinline__ void ldsm4t(uint32_t* r, uint32_t addr) {
    asm volatile("ldmatrix.sync.aligned.m8n8.x4.trans.shared.b16 {%0,%1,%2,%3}, [%4];"
        : "=r"(r[0]), "=r"(r[1]), "=r"(r[2]), "=r"(r[3]) : "r"(addr));
}

// ---------------------------------------------------------------------------
// Merged prep (R14 form): z<4 -> weight transpose+f16; z==4 -> x f32->f16
// ---------------------------------------------------------------------------
__global__ void prep_kernel(const float* __restrict__ x,
                            const float* __restrict__ Wq, const float* __restrict__ Wk,
                            const float* __restrict__ Wv, const float* __restrict__ Wo,
                            __half* __restrict__ xh,
                            __half* __restrict__ dq, __half* __restrict__ dk,
                            __half* __restrict__ dv, __half* __restrict__ dob)
{
    const int z = blockIdx.z;
    const int tx = threadIdx.x, ty = threadIdx.y;   // 32 x 8

    if (z == 4) {
        int bid = blockIdx.y * 64 + blockIdx.x;
        int i = bid * 256 + ty * 32 + tx;
        #pragma unroll
        for (int u = 0; u < 2; u++) {
            int idx = i + u * 1048576;
            float4 v = *(const float4*)(x + (size_t)idx * 4);
            uint2 o;
            o.x = packh2(v.x, v.y);
            o.y = packh2(v.z, v.w);
            *(uint2*)(xh + (size_t)idx * 4) = o;
        }
        return;
    }

    const float* src; __half* dst; int cols;
    if (z == 0)      { src = Wq; dst = dq;  cols = 2048; }
    else if (z == 1) { src = Wk; dst = dk;  cols = 512;  }
    else if (z == 2) { src = Wv; dst = dv;  cols = 512;  }
    else             { src = Wo; dst = dob; cols = 2048; }
    int bx = blockIdx.x * 32, by = blockIdx.y * 32;
    if (bx >= cols) return;

    __shared__ float t[32][33];
    #pragma unroll
    for (int j = 0; j < 32; j += 8)
        t[ty + j][tx] = src[(size_t)(by + ty + j) * cols + bx + tx];
    __syncthreads();
    #pragma unroll
    for (int j = 0; j < 32; j += 8)
        dst[(size_t)(bx + ty + j) * 2048 + by + tx] = __float2half(t[tx][ty + j]);
}

// ---------------------------------------------------------------------------
// fp16 mma.sync GEMM: K-step 32, 3-stage cp.async, ldmatrix (R12 shape).
// ROPE_K: epilogue stages tile in smem, applies RoPE across (d, d+32) pairs.
// ---------------------------------------------------------------------------
template<bool HALF_OUT, bool ROPE_K>
__device__ __forceinline__ void gemm128_h(
    const __half* __restrict__ A, const __half* __restrict__ Wt,
    void* __restrict__ C, int ldc, int row0, int wc0,
    const float* __restrict__ cosb, const float* __restrict__ sinb)
{
    extern __shared__ __align__(16) __half smh[];
    const uint32_t asb = smem_u32(smh);
    const uint32_t bsb = asb + NSTG * ASTG32 * 2;

    const int tid = threadIdx.x;
    const int wid = tid >> 5, lane = tid & 31;
    const int g = lane >> 2, c = lane & 3;
    const int wm = (wid & 1) * 64;
    const int wn = (wid >> 1) * 32;
    const int l7 = lane & 7, lb = (lane >> 3) & 1, lh = lane >> 4;

    const int lrow = tid >> 1, seg = tid & 1;
    const __half* asrc = A  + (size_t)(row0 + lrow) * 2048 + seg * 16;
    const __half* bsrc = Wt + (size_t)(wc0 + lrow) * 2048 + seg * 16;
    const uint32_t adst = asb + (lrow * 40 + seg * 16) * 2;
    const uint32_t bdst = bsb + (lrow * 40 + seg * 16) * 2;

    float acc[4][4][4];
    #pragma unroll
    for (int mt = 0; mt < 4; mt++)
        #pragma unroll
        for (int nt = 0; nt < 4; nt++)
            #pragma unroll
            for (int e = 0; e < 4; e++) acc[mt][nt][e] = 0.f;

    #pragma unroll
    for (int s = 0; s < NSTG - 1; s++) {
        cpa16(adst + s * ASTG32 * 2,      asrc + s * 32);
        cpa16(adst + s * ASTG32 * 2 + 16, asrc + s * 32 + 8);
        cpa16(bdst + s * ASTG32 * 2,      bsrc + s * 32);
        cpa16(bdst + s * ASTG32 * 2 + 16, bsrc + s * 32 + 8);
        CP_COMMIT();
    }

    int buf = 0;
    for (int i = 0; i < 64; ++i) {
        CP_WAIT(1);
        __syncthreads();

        const uint32_t Ab = asb + buf * ASTG32 * 2;
        const uint32_t Bb = bsb + buf * ASTG32 * 2;
        #pragma unroll
        for (int kc = 0; kc < 2; kc++) {
            uint32_t af[4][4], bf[2][4];
            #pragma unroll
            for (int mt = 0; mt < 4; mt++)
                ldsm4(af[mt], Ab + ((wm + mt * 16 + l7 + lb * 8) * 40 + kc * 16 + lh * 8) * 2);
            #pragma unroll
            for (int ntp = 0; ntp < 2; ntp++)
                ldsm4(bf[ntp], Bb + ((wn + ntp * 16 + lh * 8 + l7) * 40 + kc * 16 + lb * 8) * 2);
            #pragma unroll
            for (int mt = 0; mt < 4; mt++) {
                #pragma unroll
                for (int ntp = 0; ntp < 2; ntp++) {
                    mma_f16(acc[mt][ntp * 2],     af[mt], &bf[ntp][0]);
                    mma_f16(acc[mt][ntp * 2 + 1], af[mt], &bf[ntp][2]);
                }
            }
        }

        int nk = i + NSTG - 1;
        if (nk < 64) {
            int s = buf + 2 >= NSTG ? buf + 2 - NSTG : buf + 2;
            cpa16(adst + s * ASTG32 * 2,      asrc + nk * 32);
            cpa16(adst + s * ASTG32 * 2 + 16, asrc + nk * 32 + 8);
            cpa16(bdst + s * ASTG32 * 2,      bsrc + nk * 32);
            cpa16(bdst + s * ASTG32 * 2 + 16, bsrc + nk * 32 + 8);
        }
        CP_COMMIT();
        buf = buf + 1 >= NSTG ? 0 : buf + 1;
    }

    if (ROPE_K) {
        __half* st = smh;   // [128][132] = 33792 B, fits in 61440 B
        __syncthreads();    // pipeline reads done; smem free
        #pragma unroll
        for (int mt = 0; mt < 4; mt++) {
            int r = wm + mt * 16 + g;
            #pragma unroll
            for (int nt = 0; nt < 4; nt++) {
                int cl = wn + nt * 8 + 2 * c;
                *(uint32_t*)&st[r * 132 + cl] =
                    packh2(acc[mt][nt][0], acc[mt][nt][1]);
                *(uint32_t*)&st[(r + 8) * 132 + cl] =
                    packh2(acc[mt][nt][2], acc[mt][nt][3]);
            }
        }
        __syncthreads();
        __half* Ch = (__half*)C;
        for (int idx = tid; idx < 8192; idx += 256) {
            int row = idx >> 6, t6 = idx & 63;
            int hd = t6 >> 5, d = t6 & 31;
            int cl = hd * 64 + d;
            float x1 = __half2float(st[row * 132 + cl]);
            float x2 = __half2float(st[row * 132 + cl + 32]);
            int s = (row0 + row) & (S_ - 1);
            float c1 = cosb[s * 64 + d],      s1 = sinb[s * 64 + d];
            float c2 = cosb[s * 64 + d + 32], s2 = sinb[s * 64 + d + 32];
            Ch[(size_t)(row0 + row) * ldc + wc0 + cl]      = __float2half(x1 * c1 - x2 * s1);
            Ch[(size_t)(row0 + row) * ldc + wc0 + cl + 32] = __float2half(x2 * c2 + x1 * s2);
        }
        return;
    }

    #pragma unroll
    for (int mt = 0; mt < 4; mt++) {
        int r = row0 + wm + mt * 16 + g;
        #pragma unroll
        for (int nt = 0; nt < 4; nt++) {
            int col = wc0 + wn + nt * 8 + 2 * c;
            if (HALF_OUT) {
                __half* Ch = (__half*)C;
                *(uint32_t*)&Ch[(size_t)r * ldc + col] =
                    packh2(acc[mt][nt][0], acc[mt][nt][1]);
                *(uint32_t*)&Ch[(size_t)(r + 8) * ldc + col] =
                    packh2(acc[mt][nt][2], acc[mt][nt][3]);
            } else {
                float* Cf = (float*)C;
                *(float2*)&Cf[(size_t)r * ldc + col] =
                    make_float2(acc[mt][nt][0], acc[mt][nt][1]);
                *(float2*)&Cf[(size_t)(r + 8) * ldc + col] =
                    make_float2(acc[mt][nt][2], acc[mt][nt][3]);
            }
        }
    }
}

__global__ __launch_bounds__(256, 2) void qkv_gemm_h(
    const float* __restrict__ cosb, const float* __restrict__ sinb)
{
    int col0 = blockIdx.x * 128, row0 = blockIdx.y * 128;
    if (col0 < 2048) {
        gemm128_h<true, false>(g_xh, g_Wqh, g_qh, 2048, row0, col0, cosb, sinb);
    } else if (col0 < 2560) {
        gemm128_h<true, true>(g_xh, g_Wkh, g_kh, 512, row0, col0 - 2048, cosb, sinb);
    } else {
        gemm128_h<true, false>(g_xh, g_Wvh, g_vh, 512, row0, col0 - 2560, cosb, sinb);
    }
}

__global__ __launch_bounds__(256, 2) void out_gemm_h(float* __restrict__ out)
{
    int col0 = blockIdx.x * 128, row0 = blockIdx.y * 128;
    gemm128_h<false, false>(g_attnh, g_Woh, out, 2048, row0, col0, nullptr, nullptr);
}

// ---------------------------------------------------------------------------
// Flash attention fp16: 3-stage cp.async, one barrier/tile, ldmatrix,
// RoPE-Q fused, exp2 softmax via packed ex2.approx.f16x2.
// R16: prefetch for tile jt+2 issued right after the S-matmul (earlier overlap).
// ---------------------------------------------------------------------------
#define FSTG 9216   // bytes per stage per matrix: 64*72*2
#define QSCALE 0.180336880f   // 0.125 * log2(e)

__global__ __launch_bounds__(256, 2) void flash_h_kernel(
    const float* __restrict__ cosb, const float* __restrict__ sinb)
{
    extern __shared__ __align__(16) __half fsm[];
    const uint32_t skb = smem_u32(fsm);
    const uint32_t svb = skb + 3 * FSTG;

    const int tid = threadIdx.x;
    const int wid = tid >> 5, lane = tid & 31;
    const int g = lane >> 2, c = lane & 3;
    const int l7 = lane & 7, lb = (lane >> 3) & 1, lh = lane >> 4;
    const int qb = blockIdx.x, h = blockIdx.y, b = blockIdx.z;
    const int kvh = h >> 2;

    const __half* kvK = g_kh + ((size_t)(b * S_) * KVH_ + kvh) * 64;
    const __half* kvV = g_vh + ((size_t)(b * S_) * KVH_ + kvh) * 64;
    const int r0c = tid >> 3, c8 = tid & 7;

    const __half* qr = g_qh + ((size_t)(b * S_ + qb * 128 + wid * 16) * H_ + h) * 64;
    const int s0 = qb * 128 + wid * 16 + g;
    uint32_t qa[4][4];
    #pragma unroll
    for (int kc = 0; kc < 4; kc++) {
        #pragma unroll
        for (int e = 0; e < 4; e++) {
            const int rr = (e & 1) ? (g + 8) : g;
            const int sidx = (e & 1) ? (s0 + 8) : s0;
            const int d = kc * 16 + 2 * c + ((e >> 1) ? 8 : 0);
            __half2 qv = *(const __half2*)&qr[(size_t)rr * 2048 + d];
            __half2 pv = *(const __half2*)&qr[(size_t)rr * 2048 + (d ^ 32)];
            float2 cs = *(const float2*)&cosb[sidx * 64 + d];
            float2 sn = *(const float2*)&sinb[sidx * 64 + d];
            float sgn = (d < 32) ? -1.f : 1.f;
            float r0v = (__half2float(qv.x) * cs.x + sgn * __half2float(pv.x) * sn.x) * QSCALE;
            float r1v = (__half2float(qv.y) * cs.y + sgn * __half2float(pv.y) * sn.y) * QSCALE;
            qa[kc][e] = packh2(r0v, r1v);
        }
    }

    float o[8][4];
    #pragma unroll
    for (int dt = 0; dt < 8; dt++)
        #pragma unroll
        for (int e = 0; e < 4; e++) o[dt][e] = 0.f;
    float m0 = -1.0e30f, m1 = -1.0e30f, l0 = 0.f, l1 = 0.f;

    #pragma unroll
    for (int s = 0; s < 2; s++) {
        const __half* kb = kvK + (size_t)s * 64 * 512;
        const __half* vb = kvV + (size_t)s * 64 * 512;
        #pragma unroll
        for (int u = 0; u < 2; u++) {
            int r = r0c + u * 32;
            cpa16(skb + s * FSTG + (r * 72 + c8 * 8) * 2, kb + (size_t)r * 512 + c8 * 8);
            cpa16(svb + s * FSTG + (r * 72 + c8 * 8) * 2, vb + (size_t)r * 512 + c8 * 8);
        }
        CP_COMMIT();
    }

    int stage = 0;
    for (int jt = 0; jt < 16; ++jt) {
        CP_WAIT(1);
        __syncthreads();

        const uint32_t Kb = skb + stage * FSTG;
        const uint32_t Vb = svb + stage * FSTG;

        // S (log2-domain) = Q @ K^T
        float s[8][4];
        #pragma unroll
        for (int nt = 0; nt < 8; nt++)
            #pragma unroll
            for (int e = 0; e < 4; e++) s[nt][e] = 0.f;
        #pragma unroll
        for (int nt = 0; nt < 8; nt++) {
            #pragma unroll
            for (int kc2 = 0; kc2 < 2; kc2++) {
                uint32_t bk[4];
                ldsm4(bk, Kb + ((nt * 8 + l7) * 72 + kc2 * 32 + (lane >> 3) * 8) * 2);
                mma_f16(s[nt], qa[kc2 * 2],     &bk[0]);
                mma_f16(s[nt], qa[kc2 * 2 + 1], &bk[2]);
            }
        }

        // prefetch tile jt+2 NOW (target stage untouched this iteration) so the
        // loads overlap softmax + PV; commit before the heavy MUFU phase.
        if (jt + 2 < 16) {
            const int ws = (stage + 2 >= 3) ? (stage + 2 - 3) : (stage + 2);
            const __half* kb = kvK + (size_t)(jt + 2) * 64 * 512;
            const __half* vb = kvV + (size_t)(jt + 2) * 64 * 512;
            #pragma unroll
            for (int u = 0; u < 2; u++) {
                int r = r0c + u * 32;
                cpa16(skb + ws * FSTG + (r * 72 + c8 * 8) * 2, kb + (size_t)r * 512 + c8 * 8);
                cpa16(svb + ws * FSTG + (r * 72 + c8 * 8) * 2, vb + (size_t)r * 512 + c8 * 8);
            }
        }
        CP_COMMIT();

        // online softmax in exp2 domain
        float tm0 = -1.0e30f, tm1 = -1.0e30f;
        #pragma unroll
        for (int nt = 0; nt < 8; nt++) {
            tm0 = fmaxf(tm0, fmaxf(s[nt][0], s[nt][1]));
            tm1 = fmaxf(tm1, fmaxf(s[nt][2], s[nt][3]));
        }
        tm0 = fmaxf(tm0, __shfl_xor_sync(0xffffffffu, tm0, 1));
        tm0 = fmaxf(tm0, __shfl_xor_sync(0xffffffffu, tm0, 2));
        tm1 = fmaxf(tm1, __shfl_xor_sync(0xffffffffu, tm1, 1));
        tm1 = fmaxf(tm1, __shfl_xor_sync(0xffffffffu, tm1, 2));

        float nm0 = fmaxf(m0, tm0), nm1 = fmaxf(m1, tm1);
        float al0 = exp2f(m0 - nm0), al1 = exp2f(m1 - nm1);
        m0 = nm0; m1 = nm1;

        uint32_t pk0[8], pk1[8];
        float sum0 = 0.f, sum1 = 0.f;
        #pragma unroll
        for (int nt = 0; nt < 8; nt++) {
            pk0[nt] = ex2_h2(s[nt][0] - nm0, s[nt][1] - nm0);
            pk1[nt] = ex2_h2(s[nt][2] - nm1, s[nt][3] - nm1);
            float2 f0 = __half22float2(*(__half2*)&pk0[nt]);
            float2 f1 = __half22float2(*(__half2*)&pk1[nt]);
            sum0 += f0.x + f0.y;
            sum1 += f1.x + f1.y;
        }
        sum0 += __shfl_xor_sync(0xffffffffu, sum0, 1);
        sum0 += __shfl_xor_sync(0xffffffffu, sum0, 2);
        sum1 += __shfl_xor_sync(0xffffffffu, sum1, 1);
        sum1 += __shfl_xor_sync(0xffffffffu, sum1, 2);
        l0 = l0 * al0 + sum0;
        l1 = l1 * al1 + sum1;

        #pragma unroll
        for (int dt = 0; dt < 8; dt++) {
            o[dt][0] *= al0; o[dt][1] *= al0;
            o[dt][2] *= al1; o[dt][3] *= al1;
        }

        // O += P @ V
        #pragma unroll
        for (int kc = 0; kc < 4; kc++) {
            uint32_t a[4] = { pk0[2 * kc], pk1[2 * kc], pk0[2 * kc + 1], pk1[2 * kc + 1] };
            #pragma unroll
            for (int dtp = 0; dtp < 4; dtp++) {
                uint32_t bv[4];
                ldsm4t(bv, Vb + ((kc * 16 + lb * 8 + l7) * 72 + dtp * 16 + lh * 8) * 2);
                mma_f16(o[dtp * 2],     a, &bv[0]);
                mma_f16(o[dtp * 2 + 1], a, &bv[2]);
            }
        }

        stage = (stage + 1 >= 3) ? 0 : stage + 1;
    }

    float inv0 = 1.f / l0, inv1 = 1.f / l1;
    __half* obase = g_attnh + ((size_t)(b * S_ + qb * 128 + wid * 16) * H_ + h) * 64;
    #pragma unroll
    for (int dt = 0; dt < 8; dt++) {
        *(uint32_t*)&obase[(size_t)g * 2048 + dt * 8 + 2 * c] =
            packh2(o[dt][0] * inv0, o[dt][1] * inv0);
        *(uint32_t*)&obase[(size_t)(g + 8) * 2048 + dt * 8 + 2 * c] =
            packh2(o[dt][2] * inv1, o[dt][3] * inv1);
    }
}

// ---------------------------------------------------------------------------
extern "C" void kernel_launch(void* const* d_in, const int* in_sizes, int n_in,
                              void* d_out, int out_size)
{
    (void)in_sizes; (void)n_in; (void)out_size;
    const float* x   = (const float*)d_in[0];
    const float* cb  = (const float*)d_in[1];
    const float* sb  = (const float*)d_in[2];
    const float* Wq  = (const float*)d_in[3];
    const float* Wk  = (const float*)d_in[4];
    const float* Wv  = (const float*)d_in[5];
    const float* Wo  = (const float*)d_in[6];
    float* out = (float*)d_out;

    const int GEMM_SMEM  = NSTG * ASTG32 * 2 * 2;    // 61440 B -> 2 CTAs/SM
    const int FLASH_SMEM = 6 * FSTG;                  // 55296 B
    cudaFuncSetAttribute(qkv_gemm_h, cudaFuncAttributeMaxDynamicSharedMemorySize, GEMM_SMEM);
    cudaFuncSetAttribute(out_gemm_h, cudaFuncAttributeMaxDynamicSharedMemorySize, GEMM_SMEM);
    cudaFuncSetAttribute(flash_h_kernel, cudaFuncAttributeMaxDynamicSharedMemorySize, FLASH_SMEM);

    __half* xh; __half* wqh; __half* wkh; __half* wvh; __half* woh;
    cudaGetSymbolAddress((void**)&xh,  g_xh);
    cudaGetSymbolAddress((void**)&wqh, g_Wqh);
    cudaGetSymbolAddress((void**)&wkh, g_Wkh);
    cudaGetSymbolAddress((void**)&wvh, g_Wvh);
    cudaGetSymbolAddress((void**)&woh, g_Woh);

    dim3 tb(32, 8);
    prep_kernel<<<dim3(64, 64, 5), tb>>>(x, Wq, Wk, Wv, Wo, xh, wqh, wkh, wvh, woh);

    qkv_gemm_h<<<dim3(3072 / 128, 4096 / 128), 256, GEMM_SMEM>>>(cb, sb);

    flash_h_kernel<<<dim3(S_ / 128, H_, B_), 256, FLASH_SMEM>>>(cb, sb);

    out_gemm_h<<<dim3(2048 / 128, 4096 / 128), 256, GEMM_SMEM>>>(out);
}